// round 6
// baseline (speedup 1.0000x reference)
#include <cuda_runtime.h>
#include <cuda_bf16.h>
#include <stdint.h>
#include <math.h>

#define D        27
#define QB       512
#define NCLS     11
#define KNN      3
#define SLABS    148
#define TILE     64
#define RPITCH   128                  // bytes per formatted row (2 k16-block pairs)
#define TBYTES   (TILE * RPITCH)      // 8192 per tile
#define NPMAX    409600
#define SMEM_TOT (2 * TBYTES + 128)

// ---------------- static device scratch ------------------------------------
__device__ unsigned int g_scale_bits[D];
__device__ float        g_inv[D];
__device__ float        g_qm[QB * D];     // -2 * scaled query
__device__ float        g_qn[QB];
__device__ float2       g_part[(size_t)QB * SLABS * KNN];
__device__ __align__(16) uint8_t g_btiles[(size_t)NPMAX * RPITCH];

// ---------------- helpers ----------------------------------------------------
__device__ __forceinline__ uint32_t smem_u32(const void* p) {
    uint32_t a;
    asm("{ .reg .u64 t; cvta.to.shared.u64 t, %1; cvt.u32.u64 %0, t; }" : "=r"(a) : "l"(p));
    return a;
}
__device__ __forceinline__ void lds128(uint32_t& x, uint32_t& y, uint32_t& z, uint32_t& w, uint32_t a) {
    asm volatile("ld.shared.v4.b32 {%0,%1,%2,%3}, [%4];"
                 : "=r"(x), "=r"(y), "=r"(z), "=r"(w) : "r"(a));
}
__device__ __forceinline__ void sts128(uint32_t a, uint32_t w0, uint32_t w1, uint32_t w2, uint32_t w3) {
    asm volatile("st.shared.v4.b32 [%0], {%1,%2,%3,%4};"
                 :: "r"(a), "r"(w0), "r"(w1), "r"(w2), "r"(w3) : "memory");
}
__device__ __forceinline__ void cpa16(uint32_t s, const void* g) {
    asm volatile("cp.async.cg.shared.global [%0], [%1], 16;" :: "r"(s), "l"(g) : "memory");
}
#define CP_COMMIT() asm volatile("cp.async.commit_group;" ::: "memory")
#define CP_WAIT0()  asm volatile("cp.async.wait_group 0;" ::: "memory")

__device__ __forceinline__ uint32_t pk(__nv_bfloat16 a, __nv_bfloat16 b) {
    unsigned short x = *(unsigned short*)&a, y = *(unsigned short*)&b;
    return (uint32_t)x | ((uint32_t)y << 16);
}

// non-volatile MMA: pure register op, let ptxas schedule freely
#define MMA(d0,d1,d2,d3, A, B0,B1) \
    asm("mma.sync.aligned.m16n8k16.row.col.f32.bf16.bf16.f32 " \
        "{%0,%1,%2,%3}, {%4,%5,%6,%7}, {%8,%9}, {%0,%1,%2,%3};" \
        : "+f"(d0), "+f"(d1), "+f"(d2), "+f"(d3) \
        : "r"((A)[0]), "r"((A)[1]), "r"((A)[2]), "r"((A)[3]), "r"(B0), "r"(B1))

#define MMA0(d0,d1,d2,d3, A, B0,B1) \
    asm("mma.sync.aligned.m16n8k16.row.col.f32.bf16.bf16.f32 " \
        "{%0,%1,%2,%3}, {%4,%5,%6,%7}, {%8,%9}, {%10,%11,%12,%13};" \
        : "=f"(d0), "=f"(d1), "=f"(d2), "=f"(d3) \
        : "r"((A)[0]), "r"((A)[1]), "r"((A)[2]), "r"((A)[3]), "r"(B0), "r"(B1), \
          "f"(0.f), "f"(0.f), "f"(0.f), "f"(0.f))

// ---------------- small kernels ----------------------------------------------
__global__ void k_init() { if (threadIdx.x < D) g_scale_bits[threadIdx.x] = 0u; }

__global__ void k_scale(const float* __restrict__ tf, int n) {
    __shared__ unsigned int sm[D];
    if (threadIdx.x < D) sm[threadIdx.x] = 0u;
    __syncthreads();
    int i = blockIdx.x * blockDim.x + threadIdx.x;
    int col = i % D;
    int stride = gridDim.x * blockDim.x;   // multiple of 27
    float m = 0.f;
    for (; i < n; i += stride) m = fmaxf(m, fabsf(tf[i]));
    atomicMax(&sm[col], __float_as_uint(m));
    __syncthreads();
    if (threadIdx.x < D) atomicMax(&g_scale_bits[threadIdx.x], sm[threadIdx.x]);
}

__global__ void k_query(const float* __restrict__ q) {
    __shared__ float inv[D];
    int t = threadIdx.x;
    if (t < D) {
        float s = __uint_as_float(g_scale_bits[t]);
        float v = (s != 0.f) ? (1.f / s) : 0.f;
        inv[t] = v;
        g_inv[t] = v;
    }
    __syncthreads();
    float qn = 0.f;
    #pragma unroll
    for (int d = 0; d < D; ++d) {
        float v = q[t * D + d] * inv[d];
        qn = fmaf(v, v, qn);
        g_qm[t * D + d] = -2.f * v;
    }
    g_qn[t] = qn;
}

// ---------------- k_prep: format train set once (128 B per point) -------------
// Pair P0 @0:  even block = hi[0:16], odd block = hi[16:27] + xn_hi@k27 + xn_lo@k28
// Pair P1 @64: even block = lo[0:16], odd block = lo[16:27] + 0 + 0
// chunk c (c=0..3) of a pair = {we[c], we[c+4], wo[c], wo[c+4]}
__global__ void __launch_bounds__(128) k_prep(const float* __restrict__ tf, int N, int NP) {
    __shared__ float inv[D];
    const int tid = threadIdx.x;
    if (tid < D) inv[tid] = g_inv[tid];
    __syncthreads();
    const int p = blockIdx.x * 128 + tid;
    if (p >= NP) return;
    const bool valid = p < N;

    float v[27];
    float xn = 0.f;
    #pragma unroll
    for (int d = 0; d < D; ++d) {
        float x = valid ? __ldg(tf + (size_t)p * D + d) * inv[d] : 0.f;
        v[d] = x;
        xn = fmaf(x, x, xn);
    }
    if (!valid) xn = 1e30f;     // padding rows never win top-3

    __nv_bfloat16 hb[27], lb[27];
    #pragma unroll
    for (int d = 0; d < D; ++d) {
        hb[d] = __float2bfloat16(v[d]);
        lb[d] = __float2bfloat16(v[d] - __bfloat162float(hb[d]));
    }
    const __nv_bfloat16 zr = __float2bfloat16(0.f);
    __nv_bfloat16 xh = __float2bfloat16(xn);
    __nv_bfloat16 xl = __float2bfloat16(xn - __bfloat162float(xh));

    uint32_t hw[8], lw[8], ho[8], lo_[8];
    #pragma unroll
    for (int j = 0; j < 8; ++j) {
        hw[j] = pk(hb[2*j], hb[2*j+1]);
        lw[j] = pk(lb[2*j], lb[2*j+1]);
    }
    #pragma unroll
    for (int j = 0; j < 5; ++j) {
        ho[j]  = pk(hb[16+2*j], hb[17+2*j]);
        lo_[j] = pk(lb[16+2*j], lb[17+2*j]);
    }
    ho[5]  = pk(hb[26], xh); ho[6]  = pk(xl, zr); ho[7]  = 0;
    lo_[5] = pk(lb[26], zr); lo_[6] = 0;          lo_[7] = 0;

    uint4* dst = (uint4*)(g_btiles + (size_t)p * RPITCH);
    #pragma unroll
    for (int c = 0; c < 4; ++c) {
        dst[c]     = make_uint4(hw[c], hw[c+4], ho[c],  ho[c+4]);   // P0
        dst[4 + c] = make_uint4(lw[c], lw[c+4], lo_[c], lo_[c+4]);  // P1
    }
}

// ---------------- main HMMA kernel --------------------------------------------
__global__ void __launch_bounds__(128, 4)
k_hmma(int N) {
    extern __shared__ char smraw[];
    const uint32_t smb = smem_u32(smraw);
    const int tid  = threadIdx.x;
    const int w    = tid >> 5;
    const int lane = tid & 31;
    const int g    = lane >> 2;
    const int c    = lane & 3;
    const int qg   = blockIdx.x & 3;
    const int slab = blockIdx.x >> 2;
    const int qbase = qg * 128;
    const int nt = (N + TILE - 1) / TILE;

    // ---- stage A rows (128 queries), same 128B pair layout; ones at k27/k28 of hi-odd
    {
        const int q = qbase + tid;
        __nv_bfloat16 hb[27], lb[27];
        #pragma unroll
        for (int d = 0; d < D; ++d) {
            float v = g_qm[q * D + d];
            hb[d] = __float2bfloat16(v);
            lb[d] = __float2bfloat16(v - __bfloat162float(hb[d]));
        }
        const __nv_bfloat16 one = __float2bfloat16(1.f);
        const __nv_bfloat16 zr  = __float2bfloat16(0.f);
        uint32_t hw[8], lw[8], ho[8], lo_[8];
        #pragma unroll
        for (int j = 0; j < 8; ++j) {
            hw[j] = pk(hb[2*j], hb[2*j+1]);
            lw[j] = pk(lb[2*j], lb[2*j+1]);
        }
        #pragma unroll
        for (int j = 0; j < 5; ++j) {
            ho[j]  = pk(hb[16+2*j], hb[17+2*j]);
            lo_[j] = pk(lb[16+2*j], lb[17+2*j]);
        }
        ho[5]  = pk(hb[26], one); ho[6]  = pk(one, zr); ho[7]  = 0;  // ones pick up xn
        lo_[5] = pk(lb[26], zr);  lo_[6] = 0;           lo_[7] = 0;  // zeros (xn once)
        const uint32_t rowa = smb + tid * RPITCH;
        #pragma unroll
        for (int cc = 0; cc < 4; ++cc) {
            sts128(rowa +      cc*16, hw[cc], hw[cc+4], ho[cc],  ho[cc+4]);
            sts128(rowa + 64 + cc*16, lw[cc], lw[cc+4], lo_[cc], lo_[cc+4]);
        }
    }
    __syncthreads();

    // ---- persistent A fragments: 4 sets x 2 m-tiles x 4 regs
    uint32_t Ahe[2][4], Aho[2][4], Ale[2][4], Alo[2][4];
    #pragma unroll
    for (int mt = 0; mt < 2; ++mt) {
        const uint32_t b0 = smb + (uint32_t)(w * 32 + mt * 16 + g) * RPITCH + c * 16;
        lds128(Ahe[mt][0], Ahe[mt][2], Aho[mt][0], Aho[mt][2], b0);
        lds128(Ahe[mt][1], Ahe[mt][3], Aho[mt][1], Aho[mt][3], b0 + 8 * RPITCH);
        lds128(Ale[mt][0], Ale[mt][2], Alo[mt][0], Alo[mt][2], b0 + 64);
        lds128(Ale[mt][1], Ale[mt][3], Alo[mt][1], Alo[mt][3], b0 + 64 + 8 * RPITCH);
    }
    __syncthreads();

    const float INF = __int_as_float(0x7f800000);
    float t0[4], t1[4], t2[4];
    int   i0[4], i1[4], i2[4];
    #pragma unroll
    for (int s = 0; s < 4; ++s) { t0[s]=t1[s]=t2[s]=INF; i0[s]=i1[s]=i2[s]=0; }

    #define INS(v_, idx_, s_) do { \
        float _v = (v_); \
        if (_v < t2[s_]) { \
            int _ix = (idx_); \
            if (_v < t1[s_]) { \
                t2[s_] = t1[s_]; i2[s_] = i1[s_]; \
                if (_v < t0[s_]) { t1[s_]=t0[s_]; i1[s_]=i0[s_]; t0[s_]=_v; i0[s_]=_ix; } \
                else             { t1[s_]=_v; i1[s_]=_ix; } \
            } else { t2[s_] = _v; i2[s_] = _ix; } \
        } } while (0)
    #define INS2(da_, db_, s_) do { \
        if (fminf(da_, db_) < t2[s_]) { INS(da_, idx0, s_); INS(db_, idx0 + 1, s_); } } while (0)

    // ---- prologue copy (8 KB tile: 4 x cp.async.16 per thread)
    if (slab < nt) {
        const uint8_t* src = g_btiles + (size_t)slab * TBYTES;
        #pragma unroll
        for (int i = 0; i < 4; ++i) cpa16(smb + tid * 16 + i * 2048, src + tid * 16 + i * 2048);
    }
    CP_COMMIT();

    int it = 0;
    for (int t = slab; t < nt; t += SLABS, ++it) {
        CP_WAIT0();
        __syncthreads();
        const int buf = it & 1;
        const uint32_t bufb = smb + (uint32_t)buf * TBYTES;
        const int tn = t + SLABS;
        if (tn < nt) {
            const uint32_t dstb = smb + (uint32_t)(buf ^ 1) * TBYTES;
            const uint8_t* src = g_btiles + (size_t)tn * TBYTES;
            #pragma unroll
            for (int i = 0; i < 4; ++i) cpa16(dstb + tid * 16 + i * 2048, src + tid * 16 + i * 2048);
        }
        CP_COMMIT();

        const int tb = t * TILE;
        #pragma unroll 2
        for (int j = 0; j < 8; ++j) {
            const uint32_t bb = bufb + (uint32_t)(j * 8 + g) * RPITCH + c * 16;
            uint32_t be0,be1,bo0,bo1, ce0,ce1,co0,co1;
            lds128(be0, be1, bo0, bo1, bb);        // P0: hi even / hi odd(+xn)
            lds128(ce0, ce1, co0, co1, bb + 64);   // P1: lo even / lo odd
            // 4 independent chains, depth 3 each
            float x00,x01,x02,x03, y00,y01,y02,y03;
            float x10,x11,x12,x13, y10,y11,y12,y13;
            MMA0(x00,x01,x02,x03, Ahe[0], be0,be1);
            MMA0(y00,y01,y02,y03, Aho[0], bo0,bo1);
            MMA0(x10,x11,x12,x13, Ahe[1], be0,be1);
            MMA0(y10,y11,y12,y13, Aho[1], bo0,bo1);
            MMA (x00,x01,x02,x03, Ale[0], be0,be1);
            MMA (y00,y01,y02,y03, Alo[0], bo0,bo1);
            MMA (x10,x11,x12,x13, Ale[1], be0,be1);
            MMA (y10,y11,y12,y13, Alo[1], bo0,bo1);
            MMA (x00,x01,x02,x03, Ahe[0], ce0,ce1);
            MMA (y00,y01,y02,y03, Aho[0], co0,co1);
            MMA (x10,x11,x12,x13, Ahe[1], ce0,ce1);
            MMA (y10,y11,y12,y13, Aho[1], co0,co1);

            const float d00 = x00 + y00, d01 = x01 + y01;
            const float d02 = x02 + y02, d03 = x03 + y03;
            const float d10 = x10 + y10, d11 = x11 + y11;
            const float d12 = x12 + y12, d13 = x13 + y13;

            const int idx0 = tb + j * 8 + 2 * c;
            INS2(d00, d01, 0);
            INS2(d02, d03, 1);
            INS2(d10, d11, 2);
            INS2(d12, d13, 3);
        }
        __syncthreads();
    }
    #undef INS2
    #undef INS

    // ---- merge top-3 across the 4 lanes of each quad (same queries, disjoint cols)
    #pragma unroll
    for (int s = 0; s < 4; ++s) {
        #pragma unroll
        for (int off = 2; off > 0; off >>= 1) {
            float o0 = __shfl_down_sync(0xffffffffu, t0[s], off);
            float o1 = __shfl_down_sync(0xffffffffu, t1[s], off);
            float o2 = __shfl_down_sync(0xffffffffu, t2[s], off);
            int   z0 = __shfl_down_sync(0xffffffffu, i0[s], off);
            int   z1 = __shfl_down_sync(0xffffffffu, i1[s], off);
            int   z2 = __shfl_down_sync(0xffffffffu, i2[s], off);
            #define MINS(vv, zz) do { \
                float _v = (vv); int _z = (zz); \
                if (_v < t2[s] || (_v == t2[s] && _z < i2[s])) { \
                    if (_v < t1[s] || (_v == t1[s] && _z < i1[s])) { \
                        t2[s]=t1[s]; i2[s]=i1[s]; \
                        if (_v < t0[s] || (_v == t0[s] && _z < i0[s])) { t1[s]=t0[s]; i1[s]=i0[s]; t0[s]=_v; i0[s]=_z; } \
                        else { t1[s]=_v; i1[s]=_z; } \
                    } else { t2[s]=_v; i2[s]=_z; } \
                } } while (0)
            MINS(o0, z0); MINS(o1, z1); MINS(o2, z2);
            #undef MINS
        }
    }
    if ((lane & 3) == 0) {
        #pragma unroll
        for (int s = 0; s < 4; ++s) {
            const int q = qbase + w * 32 + (s >> 1) * 16 + g + (s & 1) * 8;
            float2* o = g_part + ((size_t)q * SLABS + slab) * KNN;
            o[0] = make_float2(t0[s], __int_as_float(i0[s]));
            o[1] = make_float2(t1[s], __int_as_float(i1[s]));
            o[2] = make_float2(t2[s], __int_as_float(i2[s]));
        }
    }
}

// ---------------- merge + vote -------------------------------------------------
__device__ __forceinline__ void ins3(float v, int ix,
                                     float& r0, int& y0, float& r1, int& y1,
                                     float& r2, int& y2) {
    if (v < r2 || (v == r2 && ix < y2)) {
        if (v < r1 || (v == r1 && ix < y1)) {
            r2 = r1; y2 = y1;
            if (v < r0 || (v == r0 && ix < y0)) { r1 = r0; y1 = y0; r0 = v; y0 = ix; }
            else                                 { r1 = v;  y1 = ix; }
        } else { r2 = v; y2 = ix; }
    }
}

__global__ void k_reduce(const float* __restrict__ labels, float* __restrict__ out) {
    const int q    = blockIdx.x;
    const int tid  = threadIdx.x;   // 128
    const int lane = tid & 31;
    const int wid  = tid >> 5;
    __shared__ float sd[12];
    __shared__ int   si[12];
    const float INF = __int_as_float(0x7f800000);

    float b0 = INF, b1 = INF, b2 = INF;
    int   x0 = 0,   x1 = 0,   x2 = 0;
    const float2* p = g_part + (size_t)q * SLABS * KNN;
    for (int e = tid; e < SLABS * KNN; e += 128) {
        float2 v = p[e];
        ins3(v.x, __float_as_int(v.y), b0, x0, b1, x1, b2, x2);
    }
    #pragma unroll
    for (int off = 16; off > 0; off >>= 1) {
        float o0 = __shfl_down_sync(0xffffffffu, b0, off);
        float o1 = __shfl_down_sync(0xffffffffu, b1, off);
        float o2 = __shfl_down_sync(0xffffffffu, b2, off);
        int   z0 = __shfl_down_sync(0xffffffffu, x0, off);
        int   z1 = __shfl_down_sync(0xffffffffu, x1, off);
        int   z2 = __shfl_down_sync(0xffffffffu, x2, off);
        ins3(o0, z0, b0, x0, b1, x1, b2, x2);
        ins3(o1, z1, b0, x0, b1, x1, b2, x2);
        ins3(o2, z2, b0, x0, b1, x1, b2, x2);
    }
    if (lane == 0) {
        sd[wid * 3 + 0] = b0; si[wid * 3 + 0] = x0;
        sd[wid * 3 + 1] = b1; si[wid * 3 + 1] = x1;
        sd[wid * 3 + 2] = b2; si[wid * 3 + 2] = x2;
    }
    __syncthreads();

    if (tid == 0) {
        float r0 = sd[0], r1 = sd[1], r2 = sd[2];
        int   y0 = si[0], y1 = si[1], y2 = si[2];
        #pragma unroll
        for (int e = 3; e < 12; ++e) ins3(sd[e], si[e], r0, y0, r1, y1, r2, y2);

        const float qn = g_qn[q];
        const float kd0 = sqrtf(fmaxf(r0 + qn, 0.f));
        const float kd1 = sqrtf(fmaxf(r1 + qn, 0.f));
        const float kd2 = sqrtf(fmaxf(r2 + qn, 0.f));
        out[q * KNN + 0] = kd0;
        out[q * KNN + 1] = kd1;
        out[q * KNN + 2] = kd2;

        const float w0 = (kd0 == 0.f) ? 1.f : kd0;
        const float w1 = (kd1 == 0.f) ? 1.f : kd1;
        const float w2 = (kd2 == 0.f) ? 1.f : kd2;
        const float* l0 = labels + (size_t)y0 * NCLS;
        const float* l1 = labels + (size_t)y1 * NCLS;
        const float* l2 = labels + (size_t)y2 * NCLS;

        float votes[NCLS];
        #pragma unroll
        for (int cc = 0; cc < NCLS; ++cc)
            votes[cc] = l0[cc] / w0 + l1[cc] / w1 + l2[cc] / w2;

        int am = 0; float bm = votes[0];
        #pragma unroll
        for (int cc = 1; cc < NCLS; ++cc)
            if (votes[cc] > bm) { bm = votes[cc]; am = cc; }

        const bool zero_hit = (kd0 == 0.f);
        float* ro = out + QB * KNN + q * NCLS;
        #pragma unroll
        for (int cc = 0; cc < NCLS; ++cc)
            ro[cc] = zero_hit ? l0[cc] : ((cc == am) ? 1.f : 0.f);
    }
}

// ---------------- launch --------------------------------------------------------
extern "C" void kernel_launch(void* const* d_in, const int* in_sizes, int n_in,
                              void* d_out, int out_size) {
    const float* query = (const float*)d_in[0];
    const float* tf    = (const float*)d_in[1];
    const float* tl    = (const float*)d_in[2];
    float* out = (float*)d_out;
    const int n_elems = in_sizes[1];
    const int N = n_elems / D;
    const int nt = (N + TILE - 1) / TILE;
    const int NP = nt * TILE;          // formatted points incl. tile padding

    k_init  <<<1,   32 >>>();
    k_scale <<<888, 216>>>(tf, n_elems);
    k_query <<<1,   QB >>>(query);
    k_prep  <<<(NP + 127) / 128, 128>>>(tf, N, NP);
    k_hmma  <<<SLABS * 4, 128, SMEM_TOT>>>(N);
    k_reduce<<<QB,  128>>>(tl, out);
}

// round 7
// speedup vs baseline: 1.5692x; 1.5692x over previous
#include <cuda_runtime.h>
#include <cuda_bf16.h>
#include <stdint.h>
#include <math.h>

#define D        27
#define QB       512
#define NCLS     11
#define KNN      3
#define SLABS    148           // train slabs
#define TILE     64            // train points per tile
#define PITCH    224           // bytes per staged row (56 words; conflict-free phases)
#define SMB_B1   (64 * PITCH)  // second buffer offset
#define SMB_INV  (128 * PITCH)
#define SMEM_TOT (128 * PITCH + 128)

// ---------------- static device scratch ------------------------------------
__device__ unsigned int g_scale_bits[D];
__device__ float        g_inv[D];
__device__ float        g_qm[QB * D];   // -2 * scaled query
__device__ float        g_qn[QB];
__device__ float2       g_part[(size_t)QB * SLABS * KNN];

// ---------------- helpers ----------------------------------------------------
__device__ __forceinline__ uint32_t smem_u32(const void* p) {
    uint32_t a;
    asm("{ .reg .u64 t; cvta.to.shared.u64 t, %1; cvt.u32.u64 %0, t; }" : "=r"(a) : "l"(p));
    return a;
}
__device__ __forceinline__ void lds64(uint32_t& x, uint32_t& y, uint32_t a) {
    asm volatile("ld.shared.v2.b32 {%0,%1}, [%2];" : "=r"(x), "=r"(y) : "r"(a));
}
__device__ __forceinline__ void sts128(uint32_t a, uint32_t w0, uint32_t w1, uint32_t w2, uint32_t w3) {
    asm volatile("st.shared.v4.b32 [%0], {%1,%2,%3,%4};"
                 :: "r"(a), "r"(w0), "r"(w1), "r"(w2), "r"(w3) : "memory");
}
__device__ __forceinline__ uint32_t pk(__nv_bfloat16 a, __nv_bfloat16 b) {
    unsigned short x = *(unsigned short*)&a, y = *(unsigned short*)&b;
    return (uint32_t)x | ((uint32_t)y << 16);
}
// store 8 linear k-pair words permuted: pos 2c = w[c], pos 2c+1 = w[c+4]
#define STBLK(a, W) do { \
    sts128((a),      (W)[0], (W)[4], (W)[1], (W)[5]); \
    sts128((a) + 16, (W)[2], (W)[6], (W)[3], (W)[7]); \
} while (0)

#define MMA(d0,d1,d2,d3, A0,A1,A2,A3, B0,B1) \
    asm volatile("mma.sync.aligned.m16n8k16.row.col.f32.bf16.bf16.f32 " \
        "{%0,%1,%2,%3}, {%4,%5,%6,%7}, {%8,%9}, {%0,%1,%2,%3};" \
        : "+f"(d0), "+f"(d1), "+f"(d2), "+f"(d3) \
        : "r"(A0), "r"(A1), "r"(A2), "r"(A3), "r"(B0), "r"(B1))

#define MMA0(d0,d1,d2,d3, A0,A1,A2,A3, B0,B1) \
    asm volatile("mma.sync.aligned.m16n8k16.row.col.f32.bf16.bf16.f32 " \
        "{%0,%1,%2,%3}, {%4,%5,%6,%7}, {%8,%9}, {%10,%11,%12,%13};" \
        : "=f"(d0), "=f"(d1), "=f"(d2), "=f"(d3) \
        : "r"(A0), "r"(A1), "r"(A2), "r"(A3), "r"(B0), "r"(B1), \
          "f"(0.f), "f"(0.f), "f"(0.f), "f"(0.f))

// ---------------- small kernels ----------------------------------------------
__global__ void k_init() { if (threadIdx.x < D) g_scale_bits[threadIdx.x] = 0u; }

__global__ void k_scale(const float* __restrict__ tf, int n) {
    __shared__ unsigned int sm[D];
    if (threadIdx.x < D) sm[threadIdx.x] = 0u;
    __syncthreads();
    int i = blockIdx.x * blockDim.x + threadIdx.x;
    int col = i % D;
    int stride = gridDim.x * blockDim.x;   // multiple of 27
    float m = 0.f;
    for (; i < n; i += stride) m = fmaxf(m, fabsf(tf[i]));
    atomicMax(&sm[col], __float_as_uint(m));
    __syncthreads();
    if (threadIdx.x < D) atomicMax(&g_scale_bits[threadIdx.x], sm[threadIdx.x]);
}

__global__ void k_query(const float* __restrict__ q) {
    __shared__ float inv[D];
    int t = threadIdx.x;
    if (t < D) {
        float s = __uint_as_float(g_scale_bits[t]);
        float v = (s != 0.f) ? (1.f / s) : 0.f;
        inv[t] = v;
        g_inv[t] = v;
    }
    __syncthreads();
    float qn = 0.f;
    #pragma unroll
    for (int d = 0; d < D; ++d) {
        float v = q[t * D + d] * inv[d];
        qn = fmaf(v, v, qn);
        g_qm[t * D + d] = -2.f * v;
    }
    g_qn[t] = qn;
}

// ---------------- producer: build one 64-point B tile -------------------------
__device__ __forceinline__ void produce(const float* __restrict__ tf,
                                        const float* __restrict__ inv_s,
                                        uint32_t dst, int t, int N, int tid) {
    const int pt = tid >> 1, h = tid & 1;
    const int p  = t * TILE + pt;
    const bool valid = p < N;
    const int nd = h ? 11 : 16;
    float v[16];
    #pragma unroll
    for (int d = 0; d < 16; ++d) {
        float x = 0.f;
        if (d < nd && valid) x = __ldg(tf + (size_t)p * D + h * 16 + d) * inv_s[h * 16 + d];
        v[d] = x;
    }
    float ps = 0.f;
    #pragma unroll
    for (int d = 0; d < 16; ++d) ps = fmaf(v[d], v[d], ps);
    float xn = ps + __shfl_xor_sync(0xffffffffu, ps, 1);

    __nv_bfloat16 hb[16], lb[16];
    #pragma unroll
    for (int d = 0; d < 16; ++d) {
        hb[d] = __float2bfloat16(v[d]);
        lb[d] = __float2bfloat16(v[d] - __bfloat162float(hb[d]));
    }
    const uint32_t rowa = dst + pt * PITCH;
    const __nv_bfloat16 zr = __float2bfloat16(0.f);

    if (h == 0) {
        uint32_t hw[8], lw[8];
        #pragma unroll
        for (int j = 0; j < 8; ++j) {
            hw[j] = pk(hb[2*j], hb[2*j+1]);
            lw[j] = pk(lb[2*j], lb[2*j+1]);
        }
        STBLK(rowa +   0, hw);   // s0: hi  (vs A hi)
        STBLK(rowa +  64, hw);   // s2: hi  (vs A lo)
        STBLK(rowa + 128, lw);   // s4: lo  (vs A hi)
    } else {
        if (!valid) xn = 1e30f;            // padding rows excluded via huge d2
        __nv_bfloat16 xh = __float2bfloat16(xn);
        __nv_bfloat16 xl = __float2bfloat16(xn - __bfloat162float(xh));
        uint32_t b1[8], b3[8], b5[8];
        #pragma unroll
        for (int j = 0; j < 5; ++j) {
            uint32_t hp = pk(hb[2*j], hb[2*j+1]);   // dims 16..25
            b1[j] = hp; b3[j] = hp;
            b5[j] = pk(lb[2*j], lb[2*j+1]);
        }
        b1[5] = pk(hb[10], xh); b1[6] = pk(xl, zr); b1[7] = 0;  // k26=hi26, k27=xn_hi, k28=xn_lo
        b3[5] = pk(hb[10], zr); b3[6] = 0;          b3[7] = 0;
        b5[5] = pk(lb[10], zr); b5[6] = 0;          b5[7] = 0;
        STBLK(rowa +  32, b1);   // s1
        STBLK(rowa +  96, b3);   // s3
        STBLK(rowa + 160, b5);   // s5
    }
}

// ---------------- main HMMA kernel --------------------------------------------
__global__ void __launch_bounds__(128, 4)
k_hmma(const float* __restrict__ tf, int N) {
    extern __shared__ char smraw[];
    const uint32_t smb = smem_u32(smraw);
    const int tid  = threadIdx.x;
    const int w    = tid >> 5;
    const int lane = tid & 31;
    const int g    = lane >> 2;          // row-in-8 group
    const int c    = lane & 3;           // k/col group
    const int qg   = blockIdx.x & 3;
    const int slab = blockIdx.x >> 2;
    const int qbase = qg * 128;
    const int nt = (N + TILE - 1) / TILE;
    const float* inv_s = (const float*)(smraw + SMB_INV);

    if (tid < D) ((float*)(smraw + SMB_INV))[tid] = g_inv[tid];

    // ---- stage A rows (temporarily uses the whole B region: 128 rows x 224B)
    {
        const int row = tid;
        const int q = qbase + row;
        __nv_bfloat16 hi_[27], lo_[27];
        #pragma unroll
        for (int d = 0; d < 27; ++d) {
            float v = g_qm[q * 27 + d];
            __nv_bfloat16 h = __float2bfloat16(v);
            hi_[d] = h;
            lo_[d] = __float2bfloat16(v - __bfloat162float(h));
        }
        const __nv_bfloat16 one = __float2bfloat16(1.f);
        const __nv_bfloat16 zr  = __float2bfloat16(0.f);
        uint32_t hw[8], lw[8], b1[8], b3[8], b5[8];
        #pragma unroll
        for (int j = 0; j < 8; ++j) {
            hw[j] = pk(hi_[2*j], hi_[2*j+1]);
            lw[j] = pk(lo_[2*j], lo_[2*j+1]);
        }
        #pragma unroll
        for (int j = 0; j < 5; ++j) {
            b1[j] = pk(hi_[16+2*j], hi_[17+2*j]);
            b5[j] = b1[j];
            b3[j] = pk(lo_[16+2*j], lo_[17+2*j]);
        }
        b1[5] = pk(hi_[26], one); b1[6] = pk(one, zr); b1[7] = 0;  // ones at k27,k28
        b3[5] = pk(lo_[26], zr);  b3[6] = 0;           b3[7] = 0;
        b5[5] = pk(hi_[26], zr);  b5[6] = 0;           b5[7] = 0;
        const uint32_t rowa = smb + row * PITCH;
        STBLK(rowa +   0, hw);   // s0: hi_q
        STBLK(rowa +  32, b1);   // s1: hi_q tail + ones
        STBLK(rowa +  64, lw);   // s2: lo_q
        STBLK(rowa +  96, b3);   // s3: lo_q tail
        STBLK(rowa + 128, hw);   // s4: hi_q
        STBLK(rowa + 160, b5);   // s5: hi_q tail
    }
    __syncthreads();

    // ---- load A fragments into registers (persist for whole kernel)
    uint32_t a0[2][6], a1[2][6], a2[2][6], a3[2][6];
    #pragma unroll
    for (int mt = 0; mt < 2; ++mt)
        #pragma unroll
        for (int s = 0; s < 6; ++s) {
            uint32_t base = smb + (uint32_t)(w * 32 + mt * 16 + g) * PITCH + s * 32 + c * 8;
            lds64(a0[mt][s], a2[mt][s], base);
            lds64(a1[mt][s], a3[mt][s], base + 8 * PITCH);
        }
    __syncthreads();

    const float INF = __int_as_float(0x7f800000);
    float t0[4], t1[4], t2[4];
    int   i0[4], i1[4], i2[4];
    #pragma unroll
    for (int s = 0; s < 4; ++s) { t0[s]=t1[s]=t2[s]=INF; i0[s]=i1[s]=i2[s]=0; }

    #define INS(v_, idx_, s_) do { \
        float _v = (v_); \
        if (_v < t2[s_]) { \
            int _ix = (idx_); \
            if (_v < t1[s_]) { \
                t2[s_] = t1[s_]; i2[s_] = i1[s_]; \
                if (_v < t0[s_]) { t1[s_]=t0[s_]; i1[s_]=i0[s_]; t0[s_]=_v; i0[s_]=_ix; } \
                else             { t1[s_]=_v; i1[s_]=_ix; } \
            } else { t2[s_] = _v; i2[s_] = _ix; } \
        } } while (0)
    #define INS2(da_, db_, s_) do { \
        if (fminf(da_, db_) < t2[s_]) { INS(da_, idx0, s_); INS(db_, idx0 + 1, s_); } } while (0)

    // ---- prologue: produce first tile into buffer 0
    if (slab < nt) produce(tf, inv_s, smb, slab, N, tid);
    __syncthreads();

    int it = 0;
    for (int t = slab; t < nt; t += SLABS, ++it) {
        const int buf = it & 1;
        const uint32_t bufb = smb + (uint32_t)buf * SMB_B1;
        const int tn = t + SLABS;
        if (tn < nt) produce(tf, inv_s, smb + (uint32_t)(buf ^ 1) * SMB_B1, tn, N, tid);

        // consume tile t — 4 independent chains (m-tile x even/odd k-block), depth 3
        #pragma unroll 2
        for (int j = 0; j < 8; ++j) {
            const uint32_t bb = bufb + (uint32_t)(j * 8 + g) * PITCH + c * 8;
            float x00,x01,x02,x03, y00,y01,y02,y03;
            float x10,x11,x12,x13, y10,y11,y12,y13;
            uint32_t b0_, b1_;
            lds64(b0_, b1_, bb);          // s0
            MMA0(x00,x01,x02,x03, a0[0][0],a1[0][0],a2[0][0],a3[0][0], b0_,b1_);
            MMA0(x10,x11,x12,x13, a0[1][0],a1[1][0],a2[1][0],a3[1][0], b0_,b1_);
            lds64(b0_, b1_, bb + 32);     // s1
            MMA0(y00,y01,y02,y03, a0[0][1],a1[0][1],a2[0][1],a3[0][1], b0_,b1_);
            MMA0(y10,y11,y12,y13, a0[1][1],a1[1][1],a2[1][1],a3[1][1], b0_,b1_);
            lds64(b0_, b1_, bb + 64);     // s2
            MMA (x00,x01,x02,x03, a0[0][2],a1[0][2],a2[0][2],a3[0][2], b0_,b1_);
            MMA (x10,x11,x12,x13, a0[1][2],a1[1][2],a2[1][2],a3[1][2], b0_,b1_);
            lds64(b0_, b1_, bb + 96);     // s3
            MMA (y00,y01,y02,y03, a0[0][3],a1[0][3],a2[0][3],a3[0][3], b0_,b1_);
            MMA (y10,y11,y12,y13, a0[1][3],a1[1][3],a2[1][3],a3[1][3], b0_,b1_);
            lds64(b0_, b1_, bb + 128);    // s4
            MMA (x00,x01,x02,x03, a0[0][4],a1[0][4],a2[0][4],a3[0][4], b0_,b1_);
            MMA (x10,x11,x12,x13, a0[1][4],a1[1][4],a2[1][4],a3[1][4], b0_,b1_);
            lds64(b0_, b1_, bb + 160);    // s5
            MMA (y00,y01,y02,y03, a0[0][5],a1[0][5],a2[0][5],a3[0][5], b0_,b1_);
            MMA (y10,y11,y12,y13, a0[1][5],a1[1][5],a2[1][5],a3[1][5], b0_,b1_);

            const float d00 = x00 + y00, d01 = x01 + y01;
            const float d02 = x02 + y02, d03 = x03 + y03;
            const float d10 = x10 + y10, d11 = x11 + y11;
            const float d12 = x12 + y12, d13 = x13 + y13;

            const int idx0 = t * TILE + j * 8 + 2 * c;
            INS2(d00, d01, 0);
            INS2(d02, d03, 1);
            INS2(d10, d11, 2);
            INS2(d12, d13, 3);
        }
        __syncthreads();
    }
    #undef INS2
    #undef INS

    // ---- merge top-3 across the 4 lanes of each quad (same queries, disjoint cols)
    #pragma unroll
    for (int s = 0; s < 4; ++s) {
        #pragma unroll
        for (int off = 2; off > 0; off >>= 1) {
            float o0 = __shfl_down_sync(0xffffffffu, t0[s], off);
            float o1 = __shfl_down_sync(0xffffffffu, t1[s], off);
            float o2 = __shfl_down_sync(0xffffffffu, t2[s], off);
            int   z0 = __shfl_down_sync(0xffffffffu, i0[s], off);
            int   z1 = __shfl_down_sync(0xffffffffu, i1[s], off);
            int   z2 = __shfl_down_sync(0xffffffffu, i2[s], off);
            #define MINS(vv, zz) do { \
                float _v = (vv); int _z = (zz); \
                if (_v < t2[s] || (_v == t2[s] && _z < i2[s])) { \
                    if (_v < t1[s] || (_v == t1[s] && _z < i1[s])) { \
                        t2[s]=t1[s]; i2[s]=i1[s]; \
                        if (_v < t0[s] || (_v == t0[s] && _z < i0[s])) { t1[s]=t0[s]; i1[s]=i0[s]; t0[s]=_v; i0[s]=_z; } \
                        else { t1[s]=_v; i1[s]=_z; } \
                    } else { t2[s]=_v; i2[s]=_z; } \
                } } while (0)
            MINS(o0, z0); MINS(o1, z1); MINS(o2, z2);
            #undef MINS
        }
    }
    if ((lane & 3) == 0) {
        #pragma unroll
        for (int s = 0; s < 4; ++s) {
            const int q = qbase + w * 32 + (s >> 1) * 16 + g + (s & 1) * 8;
            float2* o = g_part + ((size_t)q * SLABS + slab) * KNN;
            o[0] = make_float2(t0[s], __int_as_float(i0[s]));
            o[1] = make_float2(t1[s], __int_as_float(i1[s]));
            o[2] = make_float2(t2[s], __int_as_float(i2[s]));
        }
    }
}

// ---------------- merge + vote -------------------------------------------------
__device__ __forceinline__ void ins3(float v, int ix,
                                     float& r0, int& y0, float& r1, int& y1,
                                     float& r2, int& y2) {
    if (v < r2 || (v == r2 && ix < y2)) {
        if (v < r1 || (v == r1 && ix < y1)) {
            r2 = r1; y2 = y1;
            if (v < r0 || (v == r0 && ix < y0)) { r1 = r0; y1 = y0; r0 = v; y0 = ix; }
            else                                 { r1 = v;  y1 = ix; }
        } else { r2 = v; y2 = ix; }
    }
}

__global__ void k_reduce(const float* __restrict__ labels, float* __restrict__ out) {
    const int q    = blockIdx.x;
    const int tid  = threadIdx.x;   // 128
    const int lane = tid & 31;
    const int wid  = tid >> 5;
    __shared__ float sd[12];
    __shared__ int   si[12];
    const float INF = __int_as_float(0x7f800000);

    float b0 = INF, b1 = INF, b2 = INF;
    int   x0 = 0,   x1 = 0,   x2 = 0;
    const float2* p = g_part + (size_t)q * SLABS * KNN;
    for (int e = tid; e < SLABS * KNN; e += 128) {
        float2 v = p[e];
        ins3(v.x, __float_as_int(v.y), b0, x0, b1, x1, b2, x2);
    }
    #pragma unroll
    for (int off = 16; off > 0; off >>= 1) {
        float o0 = __shfl_down_sync(0xffffffffu, b0, off);
        float o1 = __shfl_down_sync(0xffffffffu, b1, off);
        float o2 = __shfl_down_sync(0xffffffffu, b2, off);
        int   z0 = __shfl_down_sync(0xffffffffu, x0, off);
        int   z1 = __shfl_down_sync(0xffffffffu, x1, off);
        int   z2 = __shfl_down_sync(0xffffffffu, x2, off);
        ins3(o0, z0, b0, x0, b1, x1, b2, x2);
        ins3(o1, z1, b0, x0, b1, x1, b2, x2);
        ins3(o2, z2, b0, x0, b1, x1, b2, x2);
    }
    if (lane == 0) {
        sd[wid * 3 + 0] = b0; si[wid * 3 + 0] = x0;
        sd[wid * 3 + 1] = b1; si[wid * 3 + 1] = x1;
        sd[wid * 3 + 2] = b2; si[wid * 3 + 2] = x2;
    }
    __syncthreads();

    if (tid == 0) {
        float r0 = sd[0], r1 = sd[1], r2 = sd[2];
        int   y0 = si[0], y1 = si[1], y2 = si[2];
        #pragma unroll
        for (int e = 3; e < 12; ++e) ins3(sd[e], si[e], r0, y0, r1, y1, r2, y2);

        const float qn = g_qn[q];
        const float kd0 = sqrtf(fmaxf(r0 + qn, 0.f));
        const float kd1 = sqrtf(fmaxf(r1 + qn, 0.f));
        const float kd2 = sqrtf(fmaxf(r2 + qn, 0.f));
        out[q * KNN + 0] = kd0;
        out[q * KNN + 1] = kd1;
        out[q * KNN + 2] = kd2;

        const float w0 = (kd0 == 0.f) ? 1.f : kd0;
        const float w1 = (kd1 == 0.f) ? 1.f : kd1;
        const float w2 = (kd2 == 0.f) ? 1.f : kd2;
        const float* l0 = labels + (size_t)y0 * NCLS;
        const float* l1 = labels + (size_t)y1 * NCLS;
        const float* l2 = labels + (size_t)y2 * NCLS;

        float votes[NCLS];
        #pragma unroll
        for (int cc = 0; cc < NCLS; ++cc)
            votes[cc] = l0[cc] / w0 + l1[cc] / w1 + l2[cc] / w2;

        int am = 0; float bm = votes[0];
        #pragma unroll
        for (int cc = 1; cc < NCLS; ++cc)
            if (votes[cc] > bm) { bm = votes[cc]; am = cc; }

        const bool zero_hit = (kd0 == 0.f);
        float* ro = out + QB * KNN + q * NCLS;
        #pragma unroll
        for (int cc = 0; cc < NCLS; ++cc)
            ro[cc] = zero_hit ? l0[cc] : ((cc == am) ? 1.f : 0.f);
    }
}

// ---------------- launch --------------------------------------------------------
extern "C" void kernel_launch(void* const* d_in, const int* in_sizes, int n_in,
                              void* d_out, int out_size) {
    const float* query = (const float*)d_in[0];
    const float* tf    = (const float*)d_in[1];
    const float* tl    = (const float*)d_in[2];
    float* out = (float*)d_out;
    const int n_elems = in_sizes[1];
    const int N = n_elems / D;

    k_init  <<<1,   32 >>>();
    k_scale <<<888, 216>>>(tf, n_elems);
    k_query <<<1,   QB >>>(query);
    k_hmma  <<<SLABS * 4, 128, SMEM_TOT>>>(tf, N);
    k_reduce<<<QB,  128>>>(tl, out);
}